// round 6
// baseline (speedup 1.0000x reference)
#include <cuda_runtime.h>
#include <cstdint>

#define C0 32
#define C1 16
#define FTOT 80
#define NSS 528
#define NTERMS 664
#define NGMAX 4096

#define SELU_SCALE 1.0507009873554805f
#define SELU_ALPHA 1.6732632423543772f
#define L2E        1.4426950408889634f
#define SQRT_L2E   1.2011224087864498f   /* sqrt(log2 e)            */
#define SQRT_VL2E  0.9126556632464995f   /* sqrt(log2(e)/sqrt(3))   */

// triu(row-major) flat index, compile-time
#define KS(i,j) ((i)*C0 - (i)*((i)-1)/2 + ((j)-(i)))
#define KV(i,j) (NSS + (i)*C1 - (i)*((i)-1)/2 + ((j)-(i)))

__constant__ float cW[NTERMS];
__device__ float   g_acc[NGMAX * FTOT];   // scaled weighted feature sums
__device__ float   g_z  [NGMAX];          // sum of attention weights

__device__ __forceinline__ float ex2f(float x) {
    float y;
    asm("ex2.approx.ftz.f32 %0, %1;" : "=f"(y) : "f"(x));
    return y;
}

__device__ __forceinline__ float wsum(float t) {
#pragma unroll
    for (int o = 16; o; o >>= 1) t += __shfl_xor_sync(0xFFFFFFFFu, t, o);
    return t;
}

__global__ void zero_kernel(int NG) {
    int i = blockIdx.x * 256 + threadIdx.x;
    if (i < NG * FTOT) g_acc[i] = 0.f;
    if (i < NG)        g_z[i]   = 0.f;
}

// ---- fused: per-node logit -> ex -> warp-segmented reduce -> global atomics ----
__global__ __launch_bounds__(256)
void fused_kernel(const float* __restrict__ ft, const int* __restrict__ bidx, int N)
{
    const int n0   = blockIdx.x * 256 + threadIdx.x;
    const int n    = (n0 < N) ? n0 : (N - 1);      // clamp: keep warp converged
    const bool ok  = (n0 < N);
    const int lane = threadIdx.x & 31;
    const float4* p = (const float4*)(ft + (size_t)n * FTOT);

    float s[C0], v[3 * C1];
#pragma unroll
    for (int q = 0; q < 8; ++q) {
        float4 t = __ldg(p + q);
        s[4*q+0] = t.x * SQRT_L2E; s[4*q+1] = t.y * SQRT_L2E;
        s[4*q+2] = t.z * SQRT_L2E; s[4*q+3] = t.w * SQRT_L2E;
    }
#pragma unroll
    for (int q = 0; q < 12; ++q) {
        float4 t = __ldg(p + 8 + q);
        v[4*q+0] = t.x * SQRT_VL2E; v[4*q+1] = t.y * SQRT_VL2E;
        v[4*q+2] = t.z * SQRT_VL2E; v[4*q+3] = t.w * SQRT_VL2E;
    }

    // two accumulator pairs for ILP on the lat-4 FFMA chains
    float xh0 = 0.f, xe0 = 0.f, xh1 = 0.f, xe1 = 0.f;
#pragma unroll
    for (int i = 0; i < C0; ++i)
#pragma unroll
        for (int j = i; j < C0; ++j) {
            float pl = s[i] * s[j];                  // = L2E * p_ij
            float w  = cW[KS(i, j)];                 // uniform constant load
            if ((j ^ i) & 1) {
                xh1 = fmaf(w, fmaxf(pl, 0.f), xh1);
                xe1 = fmaf(w, ex2f(fminf(pl, 0.f)), xe1);
            } else {
                xh0 = fmaf(w, fmaxf(pl, 0.f), xh0);
                xe0 = fmaf(w, ex2f(fminf(pl, 0.f)), xe0);
            }
        }
#pragma unroll
    for (int i = 0; i < C1; ++i)
#pragma unroll
        for (int j = i; j < C1; ++j) {
            float pl = v[3*i] * v[3*j];              // = L2E * (v_i.v_j)/sqrt3
            pl = fmaf(v[3*i+1], v[3*j+1], pl);
            pl = fmaf(v[3*i+2], v[3*j+2], pl);
            float w = cW[KV(i, j)];
            if ((j ^ i) & 1) {
                xh1 = fmaf(w, fmaxf(pl, 0.f), xh1);
                xe1 = fmaf(w, ex2f(fminf(pl, 0.f)), xe1);
            } else {
                xh0 = fmaf(w, fmaxf(pl, 0.f), xh0);
                xe0 = fmaf(w, ex2f(fminf(pl, 0.f)), xe0);
            }
        }

    // softmax shift-invariance: node-independent selu constant dropped.
    float earg = SELU_SCALE * fmaf(SELU_ALPHA * L2E,
                                   xe0 + xe1, xh0 + xh1);
    float ex = ok ? ex2f(earg) : 0.f;

    // ---- warp-segmented reduction (batch_index sorted) ----
    const int gi   = __ldg(&bidx[n]);
    const int gmin = __reduce_min_sync(0xFFFFFFFFu, gi);
    const int gmax = __reduce_max_sync(0xFFFFFFFFu, gi);

    for (int gg = gmin; gg <= gmax; ++gg) {          // warp-uniform, usually 1-2 iters
        float mex = (gi == gg) ? ex : 0.f;
        float r0 = 0.f, r1 = 0.f, r2 = 0.f;
#pragma unroll
        for (int f = 0; f < C0; ++f) {
            float t = wsum(mex * s[f]);
            if (lane == f) r0 = t;
        }
#pragma unroll
        for (int f = 0; f < 32; ++f) {
            float t = wsum(mex * v[f]);
            if (lane == f) r1 = t;
        }
#pragma unroll
        for (int f = 32; f < 48; ++f) {
            float t = wsum(mex * v[f]);
            if (lane == f - 32) r2 = t;
        }
        float zs = wsum(mex);

        float* dst = g_acc + (size_t)gg * FTOT;
        atomicAdd(dst + lane,      r0);
        atomicAdd(dst + 32 + lane, r1);
        if (lane < 16) atomicAdd(dst + 64 + lane, r2);
        if (lane == 0) atomicAdd(&g_z[gg], zs);
    }
}

// ---- normalize: undo pre-scales, divide by z ----
__global__ void normalize_kernel(float* __restrict__ out, int NG) {
    int idx = blockIdx.x * 256 + threadIdx.x;
    if (idx >= NG * FTOT) return;
    int g = idx / FTOT, f = idx - g * FTOT;
    float z   = g_z[g];
    float inv = (z != 0.f) ? (1.0f / z) : 0.f;       // empty graph -> zeros
    float sc  = (f < C0) ? (1.0f / SQRT_L2E) : (1.0f / SQRT_VL2E);
    out[idx] = g_acc[idx] * sc * inv;
}

extern "C" void kernel_launch(void* const* d_in, const int* in_sizes, int n_in,
                              void* d_out, int out_size)
{
    // node_ft: largest buffer; batch_index: size N int32; W: size 664.
    int ftIdx = -1; long ftSize = -1;
    for (int i = 0; i < n_in; ++i)
        if ((long)in_sizes[i] > ftSize) { ftSize = in_sizes[i]; ftIdx = i; }
    const int N = (int)(ftSize / FTOT);

    int biIdx = -1, wIdx = -1;
    for (int i = 0; i < n_in; ++i) {
        if (i == ftIdx) continue;
        if (in_sizes[i] == N)            biIdx = i;
        else if (in_sizes[i] == NTERMS)  wIdx = i;
    }

    const float* ft   = (const float*)d_in[ftIdx];
    const int*   bidx = (const int*)  d_in[biIdx];
    const float* W    = (const float*)d_in[wIdx];
    float*       out  = (float*)d_out;
    const int    NG   = out_size / FTOT;

    cudaMemcpyToSymbolAsync(cW, W, NTERMS * sizeof(float), 0,
                            cudaMemcpyDeviceToDevice, 0);
    zero_kernel<<<(NG * FTOT + 255) / 256, 256>>>(NG);
    fused_kernel<<<(N + 255) / 256, 256>>>(ft, bidx, N);
    normalize_kernel<<<(NG * FTOT + 255) / 256, 256>>>(out, NG);
}

// round 7
// speedup vs baseline: 1.4175x; 1.4175x over previous
#include <cuda_runtime.h>
#include <cstdint>

#define C0 32
#define C1 16
#define FTOT 80
#define NSS 528
#define NTERMS 664
#define NMAX 400000

#define SELU_SCALE 1.0507009873554805f
#define SELU_ALPHA 1.6732632423543772f
#define L2E        1.4426950408889634f
#define SQRT_L2E   1.2011224087864498f   /* sqrt(log2 e)            */
#define SQRT_VL2E  0.9126556632464995f   /* sqrt(log2(e)/sqrt(3))   */

// triu(row-major) flat index, compile-time
#define KS(i,j) ((i)*C0 - (i)*((i)-1)/2 + ((j)-(i)))
#define KV(i,j) (NSS + (i)*C1 - (i)*((i)-1)/2 + ((j)-(i)))

__constant__ float cW[NTERMS];
__device__ float   g_ex[NMAX];

__device__ __forceinline__ float ex2f(float x) {
    float y;
    asm("ex2.approx.ftz.f32 %0, %1;" : "=f"(y) : "f"(x));
    return y;
}

// ---- phase 1: per-node attention weight -> g_ex[n]; node-per-lane, registers ----
// (validated at ~44us, rel_err ~9e-7; MUFU/issue-bound)
__global__ __launch_bounds__(256)
void phase1(const float* __restrict__ ft, int N)
{
    const int n = blockIdx.x * 256 + threadIdx.x;
    if (n >= N) return;
    const float4* p = (const float4*)(ft + (size_t)n * FTOT);

    float xh0 = 0.f, xe0 = 0.f, xh1 = 0.f, xe1 = 0.f;

    {   // scalar-scalar terms: pl_ij = L2E * s_i*s_j via sqrt(L2E) pre-scale
        float s[C0];
#pragma unroll
        for (int q = 0; q < 8; ++q) {
            float4 t = __ldg(p + q);
            s[4*q+0] = t.x * SQRT_L2E; s[4*q+1] = t.y * SQRT_L2E;
            s[4*q+2] = t.z * SQRT_L2E; s[4*q+3] = t.w * SQRT_L2E;
        }
#pragma unroll
        for (int i = 0; i < C0; ++i)
#pragma unroll
            for (int j = i; j < C0; ++j) {
                float pl = s[i] * s[j];
                float w  = cW[KS(i, j)];              // uniform constant load
                if ((j ^ i) & 1) {
                    xh1 = fmaf(w, fmaxf(pl, 0.f), xh1);
                    xe1 = fmaf(w, ex2f(fminf(pl, 0.f)), xe1);
                } else {
                    xh0 = fmaf(w, fmaxf(pl, 0.f), xh0);
                    xe0 = fmaf(w, ex2f(fminf(pl, 0.f)), xe0);
                }
            }
    }
    {   // vector-vector terms: pl_ij = L2E * (v_i . v_j)/sqrt(3)
        float v[3 * C1];
#pragma unroll
        for (int q = 0; q < 12; ++q) {
            float4 t = __ldg(p + 8 + q);
            v[4*q+0] = t.x * SQRT_VL2E; v[4*q+1] = t.y * SQRT_VL2E;
            v[4*q+2] = t.z * SQRT_VL2E; v[4*q+3] = t.w * SQRT_VL2E;
        }
#pragma unroll
        for (int i = 0; i < C1; ++i)
#pragma unroll
            for (int j = i; j < C1; ++j) {
                float pl = v[3*i] * v[3*j];
                pl = fmaf(v[3*i+1], v[3*j+1], pl);
                pl = fmaf(v[3*i+2], v[3*j+2], pl);
                float w = cW[KV(i, j)];
                if ((j ^ i) & 1) {
                    xh1 = fmaf(w, fmaxf(pl, 0.f), xh1);
                    xe1 = fmaf(w, ex2f(fminf(pl, 0.f)), xe1);
                } else {
                    xh0 = fmaf(w, fmaxf(pl, 0.f), xh0);
                    xe0 = fmaf(w, ex2f(fminf(pl, 0.f)), xe0);
                }
            }
    }
    // softmax shift-invariance: node-independent selu constant dropped.
    float xh = xh0 + xh1, xe = xe0 + xe1;
    float earg = SELU_SCALE * fmaf(SELU_ALPHA * L2E, xe, xh);
    g_ex[n] = ex2f(earg);
}

// ---- phase 2: per-graph weighted segment sum, MLP-unrolled x4 ----
// Warp-per-node addressing (proven best); 4 nodes in flight per warp ->
// ~12 independent LDGs outstanding to cover DRAM latency.
__global__ __launch_bounds__(256)
void phase2(const float* __restrict__ ft, const int* __restrict__ bidx,
            float* __restrict__ out, int N)
{
    __shared__ float s_acc[FTOT];
    __shared__ float s_z;
    __shared__ int   s_seg[2];

    const int tid  = threadIdx.x;
    const int wid  = tid >> 5;
    const int lane = tid & 31;
    const int g    = blockIdx.x;

    if (tid < FTOT) s_acc[tid] = 0.f;
    if (tid == 0)   s_z = 0.f;
    if (tid < 2) {
        int target = g + tid;
        int lo = 0, hi = N;
        while (lo < hi) {
            int mid = (lo + hi) >> 1;
            bool lt = (bidx[mid] < target);
            lo = lt ? mid + 1 : lo;
            hi = lt ? hi : mid;
        }
        s_seg[tid] = lo;
    }
    __syncthreads();
    const int start = s_seg[0], end = s_seg[1];

    float a0 = 0.f, a1 = 0.f, a2 = 0.f, zacc = 0.f;

    int n = start + wid;
    // main body: 4 nodes per warp-iteration (stride 8 warps * 4)
    for (; n + 24 < end; n += 32) {
        float ex0 = __ldg(&g_ex[n]);
        float ex1 = __ldg(&g_ex[n +  8]);
        float ex2 = __ldg(&g_ex[n + 16]);
        float ex3 = __ldg(&g_ex[n + 24]);
        const float* p0 = ft + (size_t)(n     ) * FTOT;
        const float* p1 = ft + (size_t)(n +  8) * FTOT;
        const float* p2 = ft + (size_t)(n + 16) * FTOT;
        const float* p3 = ft + (size_t)(n + 24) * FTOT;
        // issue all independent loads up front (MLP)
        float u00 = __ldg(p0 + lane), u01 = __ldg(p0 + lane + 32);
        float u10 = __ldg(p1 + lane), u11 = __ldg(p1 + lane + 32);
        float u20 = __ldg(p2 + lane), u21 = __ldg(p2 + lane + 32);
        float u30 = __ldg(p3 + lane), u31 = __ldg(p3 + lane + 32);
        float u02 = 0.f, u12 = 0.f, u22 = 0.f, u32 = 0.f;
        if (lane < 16) {
            u02 = __ldg(p0 + lane + 64);
            u12 = __ldg(p1 + lane + 64);
            u22 = __ldg(p2 + lane + 64);
            u32 = __ldg(p3 + lane + 64);
        }
        a0 = fmaf(ex0, u00, a0); a1 = fmaf(ex0, u01, a1); a2 = fmaf(ex0, u02, a2);
        a0 = fmaf(ex1, u10, a0); a1 = fmaf(ex1, u11, a1); a2 = fmaf(ex1, u12, a2);
        a0 = fmaf(ex2, u20, a0); a1 = fmaf(ex2, u21, a1); a2 = fmaf(ex2, u22, a2);
        a0 = fmaf(ex3, u30, a0); a1 = fmaf(ex3, u31, a1); a2 = fmaf(ex3, u32, a2);
        zacc += (ex0 + ex1) + (ex2 + ex3);
    }
    // remainder
    for (; n < end; n += 8) {
        float ex = __ldg(&g_ex[n]);
        const float* p = ft + (size_t)n * FTOT;
        a0 = fmaf(ex, __ldg(p + lane),      a0);
        a1 = fmaf(ex, __ldg(p + lane + 32), a1);
        if (lane < 16) a2 = fmaf(ex, __ldg(p + lane + 64), a2);
        zacc += ex;
    }

    atomicAdd(&s_acc[lane],      a0);
    atomicAdd(&s_acc[lane + 32], a1);
    if (lane < 16) atomicAdd(&s_acc[lane + 64], a2);
    if (lane == 0) atomicAdd(&s_z, zacc);
    __syncthreads();

    float z   = s_z;
    float inv = (z != 0.f) ? (1.0f / z) : 0.f;   // empty graph -> zeros
    if (tid < FTOT) out[(size_t)g * FTOT + tid] = s_acc[tid] * inv;
}

extern "C" void kernel_launch(void* const* d_in, const int* in_sizes, int n_in,
                              void* d_out, int out_size)
{
    // node_ft: largest buffer; batch_index: size N int32; W: size 664.
    int ftIdx = -1; long ftSize = -1;
    for (int i = 0; i < n_in; ++i)
        if ((long)in_sizes[i] > ftSize) { ftSize = in_sizes[i]; ftIdx = i; }
    const int N = (int)(ftSize / FTOT);

    int biIdx = -1, wIdx = -1;
    for (int i = 0; i < n_in; ++i) {
        if (i == ftIdx) continue;
        if (in_sizes[i] == N)            biIdx = i;
        else if (in_sizes[i] == NTERMS)  wIdx = i;
    }

    const float* ft   = (const float*)d_in[ftIdx];
    const int*   bidx = (const int*)  d_in[biIdx];
    const float* W    = (const float*)d_in[wIdx];
    float*       out  = (float*)d_out;
    const int    NG   = out_size / FTOT;

    cudaMemcpyToSymbolAsync(cW, W, NTERMS * sizeof(float), 0,
                            cudaMemcpyDeviceToDevice, 0);
    phase1<<<(N + 255) / 256, 256>>>(ft, N);
    phase2<<<NG, 256>>>(ft, bidx, out, N);
}

// round 8
// speedup vs baseline: 1.6008x; 1.1293x over previous
#include <cuda_runtime.h>
#include <cstdint>

#define C0 32
#define C1 16
#define FTOT 80
#define NSS 528
#define NTERMS 664
#define NGMAX 4096

#define SELU_SCALE 1.0507009873554805f
#define SELU_ALPHA 1.6732632423543772f
#define L2E        1.4426950408889634f
#define SQRT_L2E   1.2011224087864498f   /* sqrt(log2 e)            */
#define SQRT_VL2E  0.9126556632464995f   /* sqrt(log2(e)/sqrt(3))   */

// triu(row-major) flat index, compile-time
#define KS(i,j) ((i)*C0 - (i)*((i)-1)/2 + ((j)-(i)))
#define KV(i,j) (NSS + (i)*C1 - (i)*((i)-1)/2 + ((j)-(i)))

__constant__ float cW[NTERMS];
__device__ float   g_acc[NGMAX * FTOT];   // per-graph weighted feature sums
__device__ float   g_z  [NGMAX];          // per-graph sum of attention weights

__device__ __forceinline__ float ex2f(float x) {
    float y;
    asm("ex2.approx.ftz.f32 %0, %1;" : "=f"(y) : "f"(x));
    return y;
}

__global__ void zero_kernel(int NG) {
    int i = blockIdx.x * 256 + threadIdx.x;
    if (i < NG * FTOT) g_acc[i] = 0.f;
    if (i < NG)        g_z[i]   = 0.f;
}

// ---- fused kernel: 256 nodes per block ----
// Step 1 (node-per-thread): compute attention weight ex[n] with node features
//   in registers (validated phase1 body; MUFU/issue-bound, rel_err ~9e-7).
// Step 2 (warp-per-node): weighted per-graph feature sums, re-reading the
//   SAME 80KB of node rows this block just loaded -> L1 hits, no 2nd HBM pass.
__global__ __launch_bounds__(256)
void fused_kernel(const float* __restrict__ ft, const int* __restrict__ bidx, int N)
{
    __shared__ float s_ex [256];
    __shared__ int   s_bi [256];
    __shared__ float s_acc[FTOT];
    __shared__ float s_z;
    __shared__ int   s_lo, s_hi;

    const int tid  = threadIdx.x;
    const int wid  = tid >> 5;
    const int lane = tid & 31;
    const int n0   = blockIdx.x * 256;
    const int count = min(256, N - n0);
    const bool ok  = (tid < count);
    const int n    = n0 + (ok ? tid : (count - 1));   // clamp keeps warps converged

    // ---------- step 1: per-node logit -> ex ----------
    {
        const float4* p = (const float4*)(ft + (size_t)n * FTOT);
        float xh0 = 0.f, xe0 = 0.f, xh1 = 0.f, xe1 = 0.f;
        {
            float s[C0];
#pragma unroll
            for (int q = 0; q < 8; ++q) {
                float4 t = __ldg(p + q);
                s[4*q+0] = t.x * SQRT_L2E; s[4*q+1] = t.y * SQRT_L2E;
                s[4*q+2] = t.z * SQRT_L2E; s[4*q+3] = t.w * SQRT_L2E;
            }
#pragma unroll
            for (int i = 0; i < C0; ++i)
#pragma unroll
                for (int j = i; j < C0; ++j) {
                    float pl = s[i] * s[j];            // = L2E * p_ij
                    float w  = cW[KS(i, j)];
                    if ((j ^ i) & 1) {
                        xh1 = fmaf(w, fmaxf(pl, 0.f), xh1);
                        xe1 = fmaf(w, ex2f(fminf(pl, 0.f)), xe1);
                    } else {
                        xh0 = fmaf(w, fmaxf(pl, 0.f), xh0);
                        xe0 = fmaf(w, ex2f(fminf(pl, 0.f)), xe0);
                    }
                }
        }
        {
            float v[3 * C1];
#pragma unroll
            for (int q = 0; q < 12; ++q) {
                float4 t = __ldg(p + 8 + q);
                v[4*q+0] = t.x * SQRT_VL2E; v[4*q+1] = t.y * SQRT_VL2E;
                v[4*q+2] = t.z * SQRT_VL2E; v[4*q+3] = t.w * SQRT_VL2E;
            }
#pragma unroll
            for (int i = 0; i < C1; ++i)
#pragma unroll
                for (int j = i; j < C1; ++j) {
                    float pl = v[3*i] * v[3*j];        // = L2E*(v_i.v_j)/sqrt3
                    pl = fmaf(v[3*i+1], v[3*j+1], pl);
                    pl = fmaf(v[3*i+2], v[3*j+2], pl);
                    float w = cW[KV(i, j)];
                    if ((j ^ i) & 1) {
                        xh1 = fmaf(w, fmaxf(pl, 0.f), xh1);
                        xe1 = fmaf(w, ex2f(fminf(pl, 0.f)), xe1);
                    } else {
                        xh0 = fmaf(w, fmaxf(pl, 0.f), xh0);
                        xe0 = fmaf(w, ex2f(fminf(pl, 0.f)), xe0);
                    }
                }
        }
        // softmax shift-invariance: node-independent selu constant dropped.
        float earg = SELU_SCALE * fmaf(SELU_ALPHA * L2E, xe0 + xe1, xh0 + xh1);
        s_ex[tid] = ok ? ex2f(earg) : 0.f;
        s_bi[tid] = __ldg(&bidx[n]);                   // clamped for tails
    }
    __syncthreads();

    // ---------- step 2: per-graph weighted sums over this block's nodes ----------
    const int g0 = s_bi[0];
    const int g1 = s_bi[count - 1];
    const int mybi = s_bi[tid];

    for (int g = g0; g <= g1; ++g) {                   // ~2 graphs per block
        if (tid == 0) { s_lo = count; s_hi = 0; s_z = 0.f; }
        if (tid < FTOT) s_acc[tid] = 0.f;
        __syncthreads();
        if (ok && mybi == g) {                         // contiguous (sorted)
            atomicMin(&s_lo, tid);
            atomicMax(&s_hi, tid + 1);
        }
        __syncthreads();
        const int lo = s_lo, hi = s_hi;

        float a0 = 0.f, a1 = 0.f, a2 = 0.f, zacc = 0.f;
        for (int node = lo + wid; node < hi; node += 8) {
            const float* p = ft + (size_t)(n0 + node) * FTOT;   // L1-resident
            float ex = s_ex[node];                              // LDS broadcast
            a0 = fmaf(ex, __ldg(p + lane),      a0);
            a1 = fmaf(ex, __ldg(p + lane + 32), a1);
            if (lane < 16) a2 = fmaf(ex, __ldg(p + lane + 64), a2);
            zacc += ex;
        }
        atomicAdd(&s_acc[lane],      a0);
        atomicAdd(&s_acc[lane + 32], a1);
        if (lane < 16) atomicAdd(&s_acc[lane + 64], a2);
        if (lane == 0) atomicAdd(&s_z, zacc);
        __syncthreads();

        if (tid < FTOT) atomicAdd(&g_acc[(size_t)g * FTOT + tid], s_acc[tid]);
        if (tid == FTOT) atomicAdd(&g_z[g], s_z);
        __syncthreads();                               // s_acc reused next graph
    }
}

// ---- normalize: divide by z (raw features accumulated -> no unscale) ----
__global__ void normalize_kernel(float* __restrict__ out, int NG) {
    int idx = blockIdx.x * 256 + threadIdx.x;
    if (idx >= NG * FTOT) return;
    int g = idx / FTOT;
    float z   = g_z[g];
    float inv = (z != 0.f) ? (1.0f / z) : 0.f;         // empty graph -> zeros
    out[idx] = g_acc[idx] * inv;
}

extern "C" void kernel_launch(void* const* d_in, const int* in_sizes, int n_in,
                              void* d_out, int out_size)
{
    // node_ft: largest buffer; batch_index: size N int32; W: size 664.
    int ftIdx = -1; long ftSize = -1;
    for (int i = 0; i < n_in; ++i)
        if ((long)in_sizes[i] > ftSize) { ftSize = in_sizes[i]; ftIdx = i; }
    const int N = (int)(ftSize / FTOT);

    int biIdx = -1, wIdx = -1;
    for (int i = 0; i < n_in; ++i) {
        if (i == ftIdx) continue;
        if (in_sizes[i] == N)            biIdx = i;
        else if (in_sizes[i] == NTERMS)  wIdx = i;
    }

    const float* ft   = (const float*)d_in[ftIdx];
    const int*   bidx = (const int*)  d_in[biIdx];
    const float* W    = (const float*)d_in[wIdx];
    float*       out  = (float*)d_out;
    const int    NG   = out_size / FTOT;

    cudaMemcpyToSymbolAsync(cW, W, NTERMS * sizeof(float), 0,
                            cudaMemcpyDeviceToDevice, 0);
    zero_kernel<<<(NG * FTOT + 255) / 256, 256>>>(NG);
    fused_kernel<<<(N + 255) / 256, 256>>>(ft, bidx, N);
    normalize_kernel<<<(NG * FTOT + 255) / 256, 256>>>(out, NG);
}

// round 9
// speedup vs baseline: 1.6343x; 1.0209x over previous
#include <cuda_runtime.h>
#include <cstdint>

#define C0 32
#define C1 16
#define FTOT 80
#define NSS 528
#define NTERMS 664
#define NGMAX 4096

#define SELU_SCALE 1.0507009873554805f
#define SELU_ALPHA 1.6732632423543772f
#define L2E        1.4426950408889634f
#define SQRT_L2E   1.2011224087864498f   /* sqrt(log2 e)          */
#define SQRT_VL2E  0.9126556632464995f   /* sqrt(log2(e)/sqrt(3)) */

// triu(row-major) flat index, compile-time
#define KS(i,j) ((i)*C0 - (i)*((i)-1)/2 + ((j)-(i)))
#define KV(i,j) (NSS + (i)*C1 - (i)*((i)-1)/2 + ((j)-(i)))

typedef unsigned long long ull;

__constant__ __align__(8) float cW[NTERMS];
__device__ float g_acc[NGMAX * FTOT];   // per-graph weighted feature sums
__device__ float g_z  [NGMAX];          // per-graph sum of attention weights

// ---------- packed f32x2 / f16x2 helpers (sm_103a) ----------
__device__ __forceinline__ float ex2f(float x) {
    float y; asm("ex2.approx.ftz.f32 %0, %1;" : "=f"(y) : "f"(x)); return y;
}
__device__ __forceinline__ ull pk(float lo, float hi) {
    ull r; asm("mov.b64 %0, {%1, %2};" : "=l"(r) : "f"(lo), "f"(hi)); return r;
}
__device__ __forceinline__ void up(ull a, float& lo, float& hi) {
    asm("mov.b64 {%0, %1}, %2;" : "=f"(lo), "=f"(hi) : "l"(a));
}
__device__ __forceinline__ float geth(ull a, int sel) {
    float lo, hi; up(a, lo, hi); return sel ? hi : lo;
}
__device__ __forceinline__ ull mul2(ull a, ull b) {
    ull r; asm("mul.rn.f32x2 %0, %1, %2;" : "=l"(r) : "l"(a), "l"(b)); return r;
}
__device__ __forceinline__ ull fma2(ull a, ull b, ull c) {
    ull r; asm("fma.rn.f32x2 %0, %1, %2, %3;" : "=l"(r) : "l"(a), "l"(b), "l"(c)); return r;
}
// (ea,eb) = (min(2^a,1), min(2^b,1)) via one f16x2 MUFU (R4-validated path).
__device__ __forceinline__ void exp2c2(float a, float b, float& ea, float& eb) {
    asm("{\n\t"
        ".reg .b16 l, h;\n\t"
        ".reg .b32 t;\n\t"
        "cvt.rn.f16x2.f32 t, %3, %2;\n\t"
        "ex2.approx.f16x2 t, t;\n\t"
        "min.f16x2 t, t, %4;\n\t"
        "mov.b32 {l, h}, t;\n\t"
        "cvt.f32.f16 %0, l;\n\t"
        "cvt.f32.f16 %1, h;\n\t"
        "}"
        : "=f"(ea), "=f"(eb) : "f"(a), "f"(b), "r"(0x3C003C00u));
}
// weight pair (cW[k], cW[k+1]); v2 constant load when 8B-aligned (k compile-time)
__device__ __forceinline__ ull loadw2(int k) {
    if ((k & 1) == 0) { float2 t = *(const float2*)&cW[k]; return pk(t.x, t.y); }
    return pk(cW[k], cW[k + 1]);
}
// packed term-pair: products prod2=(pla,plb), weights w2=(wa,wb)
__device__ __forceinline__ void pacc2(ull prod2, ull w2, ull& ah, ull& ae) {
    float pa, pb; up(prod2, pa, pb);
    ah = fma2(w2, pk(fmaxf(pa, 0.f), fmaxf(pb, 0.f)), ah);
    float ea, eb; exp2c2(pa, pb, ea, eb);
    ae = fma2(w2, pk(ea, eb), ae);
}
// scalar term (row-peel for alignment)
__device__ __forceinline__ void pacc1(float pl, float w, float& xh, float& xe) {
    xh = fmaf(w, fmaxf(pl, 0.f), xh);
    xe = fmaf(w, ex2f(fminf(pl, 0.f)), xe);
}

// ---- fused kernel: 256 nodes per block ----
__global__ __launch_bounds__(256, 2)
void fused_kernel(const float* __restrict__ ft, const int* __restrict__ bidx, int N)
{
    __shared__ float s_ex [256];
    __shared__ int   s_bi [256];
    __shared__ float s_acc[FTOT];
    __shared__ float s_z;
    __shared__ int   s_lo, s_hi;

    const int tid  = threadIdx.x;
    const int wid  = tid >> 5;
    const int lane = tid & 31;
    const int n0   = blockIdx.x * 256;
    const int count = min(256, N - n0);
    const bool ok  = (tid < count);
    const int n    = n0 + (ok ? tid : (count - 1));   // clamp keeps warps converged

    // ---------- step 1: per-node logit -> ex (packed pipeline) ----------
    {
        const float4* p = (const float4*)(ft + (size_t)n * FTOT);
        ull ah = 0, ae = 0;               // packed (lo,hi) fp32 accumulators
        float xh_s = 0.f, xe_s = 0.f;     // scalar-peel accumulators

        {   // scalar-scalar block: s2[m] = L2E-prescaled (s_{2m}, s_{2m+1})
            ull s2[16];
            const ull CS = pk(SQRT_L2E, SQRT_L2E);
#pragma unroll
            for (int q = 0; q < 8; ++q) {
                float4 t = __ldg(p + q);
                s2[2*q]   = mul2(pk(t.x, t.y), CS);
                s2[2*q+1] = mul2(pk(t.z, t.w), CS);
            }
#pragma unroll
            for (int i = 0; i < C0; ++i) {
                const float si = geth(s2[i >> 1], i & 1);
                if (i & 1)                            // peel (i,i): aligns pairs
                    pacc1(si * si, cW[KS(i, i)], xh_s, xe_s);
                const ull sii = pk(si, si);
                const int m0 = (i + (i & 1)) >> 1;
#pragma unroll
                for (int m = m0; m < 16; ++m)         // pair (j,j+1)=(2m,2m+1)
                    pacc2(mul2(sii, s2[m]), loadw2(KS(i, 2*m)), ah, ae);
            }
        }
        {   // vector-vector block: component-paired over j
            float v[3 * C1];
#pragma unroll
            for (int q = 0; q < 12; ++q) {
                float4 t = __ldg(p + 8 + q);
                v[4*q+0] = t.x * SQRT_VL2E; v[4*q+1] = t.y * SQRT_VL2E;
                v[4*q+2] = t.z * SQRT_VL2E; v[4*q+3] = t.w * SQRT_VL2E;
            }
            ull x2[8], y2[8], z2[8];
#pragma unroll
            for (int m = 0; m < 8; ++m) {
                x2[m] = pk(v[6*m],     v[6*m+3]);
                y2[m] = pk(v[6*m + 1], v[6*m+4]);
                z2[m] = pk(v[6*m + 2], v[6*m+5]);
            }
#pragma unroll
            for (int i = 0; i < C1; ++i) {
                const float vx = v[3*i], vy = v[3*i+1], vz = v[3*i+2];
                if (i & 1)                            // peel (i,i)
                    pacc1(fmaf(vz, vz, fmaf(vy, vy, vx * vx)),
                          cW[KV(i, i)], xh_s, xe_s);
                const ull xi = pk(vx, vx), yi = pk(vy, vy), zi = pk(vz, vz);
                const int m0 = (i + (i & 1)) >> 1;
#pragma unroll
                for (int m = m0; m < 8; ++m) {
                    ull d = mul2(xi, x2[m]);
                    d = fma2(yi, y2[m], d);
                    d = fma2(zi, z2[m], d);
                    pacc2(d, loadw2(KV(i, 2*m)), ah, ae);
                }
            }
        }
        float hlo, hhi, elo, ehi;
        up(ah, hlo, hhi); up(ae, elo, ehi);
        float xh = xh_s + (hlo + hhi);
        float xe = xe_s + (elo + ehi);
        // softmax shift-invariance: node-independent selu constant dropped.
        float earg = SELU_SCALE * fmaf(SELU_ALPHA * L2E, xe, xh);
        s_ex[tid] = ok ? ex2f(earg) : 0.f;
        s_bi[tid] = __ldg(&bidx[n]);
    }
    __syncthreads();

    // ---------- step 2: per-graph weighted sums over this block's nodes ----------
    const int g0 = s_bi[0];
    const int g1 = s_bi[count - 1];
    const int mybi = s_bi[tid];

    for (int g = g0; g <= g1; ++g) {                  // ~2 graphs per block
        if (tid == 0) { s_lo = count; s_hi = 0; s_z = 0.f; }
        if (tid < FTOT) s_acc[tid] = 0.f;
        __syncthreads();
        if (ok && mybi == g) {
            atomicMin(&s_lo, tid);
            atomicMax(&s_hi, tid + 1);
        }
        __syncthreads();
        const int lo = s_lo, hi = s_hi;

        float a0 = 0.f, a1 = 0.f, a2 = 0.f, zacc = 0.f;
        for (int node = lo + wid; node < hi; node += 8) {
            const float* pp = ft + (size_t)(n0 + node) * FTOT;  // L1-resident
            float ex = s_ex[node];
            a0 = fmaf(ex, __ldg(pp + lane),      a0);
            a1 = fmaf(ex, __ldg(pp + lane + 32), a1);
            if (lane < 16) a2 = fmaf(ex, __ldg(pp + lane + 64), a2);
            zacc += ex;
        }
        atomicAdd(&s_acc[lane],      a0);
        atomicAdd(&s_acc[lane + 32], a1);
        if (lane < 16) atomicAdd(&s_acc[lane + 64], a2);
        if (lane == 0) atomicAdd(&s_z, zacc);
        __syncthreads();

        if (tid < FTOT) atomicAdd(&g_acc[(size_t)g * FTOT + tid], s_acc[tid]);
        if (tid == FTOT) atomicAdd(&g_z[g], s_z);
        __syncthreads();
    }
}

// ---- normalize + re-zero (keeps accumulators zero for the next replay;
//      initial zero comes from static initialization of __device__ globals) ----
__global__ void normalize_kernel(float* __restrict__ out, int NG) {
    int idx = blockIdx.x * 256 + threadIdx.x;
    if (idx >= NG * FTOT) return;
    int g = idx / FTOT, f = idx - g * FTOT;
    float z   = g_z[g];
    float inv = (z != 0.f) ? (1.0f / z) : 0.f;        // empty graph -> zeros
    out[idx] = g_acc[idx] * inv;
    g_acc[idx] = 0.f;
    if (f == 0) g_z[g] = 0.f;
}

extern "C" void kernel_launch(void* const* d_in, const int* in_sizes, int n_in,
                              void* d_out, int out_size)
{
    // node_ft: largest buffer; batch_index: size N int32; W: size 664.
    int ftIdx = -1; long ftSize = -1;
    for (int i = 0; i < n_in; ++i)
        if ((long)in_sizes[i] > ftSize) { ftSize = in_sizes[i]; ftIdx = i; }
    const int N = (int)(ftSize / FTOT);

    int biIdx = -1, wIdx = -1;
    for (int i = 0; i < n_in; ++i) {
        if (i == ftIdx) continue;
        if (in_sizes[i] == N)            biIdx = i;
        else if (in_sizes[i] == NTERMS)  wIdx = i;
    }

    const float* ft   = (const float*)d_in[ftIdx];
    const int*   bidx = (const int*)  d_in[biIdx];
    const float* W    = (const float*)d_in[wIdx];
    float*       out  = (float*)d_out;
    const int    NG   = out_size / FTOT;

    cudaMemcpyToSymbolAsync(cW, W, NTERMS * sizeof(float), 0,
                            cudaMemcpyDeviceToDevice, 0);
    fused_kernel<<<(N + 255) / 256, 256>>>(ft, bidx, N);
    normalize_kernel<<<(NG * FTOT + 255) / 256, 256>>>(out, NG);
}